// round 9
// baseline (speedup 1.0000x reference)
#include <cuda_runtime.h>
#include <cuda_pipeline.h>

// ParallelBellowsLayers: per-channel 1->16->1 MLP with ReLU, C=40000, B=128, E=16.
// out[b,c] = relu( sum_e relu(x[b,c]*w1[c,e]+b1[c,e]) * w2[c,e] + b2[c] )
// Output (B,2,20000) == (B,C) row-major -> elementwise in x's layout.
//
// b1[c,:]==0 (this dataset) => sum_e relu(x*w1e)*w2e == x * (x>0 ? s_pos : s_neg).
//
// R6-R8 post-mortem: every LDG-based variant plateaus at ~11us with ALL
// resources <50% busy -- register-coupled loads issue in bursts, the warp
// blocks on the scoreboard, the memory queue drains. This version decouples
// load issue from consumption: x is staged through smem via cp.async.cg
// (LDGSTS, fire-and-forget, L1-bypass) in a depth-4 per-thread pipeline.
// Each thread copies and later consumes ITS OWN 16B, so no __syncthreads --
// only per-thread __pipeline_wait_prior. Params come from a small precompute
// kernel (NaN-flag in s_pos routes nonzero-b1 / non-finite channels to an
// exact fallback; never taken on this dataset).

#define NGENES 20000
#define NTECH  2
#define CC     (NGENES * NTECH)    // 40000 channels
#define BB     128                 // batch rows
#define EE     16
#define NG     (CC / 4)            // 10000 float4 channel-groups
#define GRPB   32                  // channel-groups per block (128 channels)
#define NTHR   256
#define RSPLIT 2                   // row split across blockIdx.y
#define ROWSB  (BB / RSPLIT)       // 64 rows per block
#define SLICES 8                   // row slices (one per warp)
#define NSTAGE (ROWSB / SLICES)    // 8 stages, 8 rows each
#define DEPTH  4                   // cp.async pipeline depth

// SoA per-channel params (NaN in g_sp[c] => exact-fallback channel)
__device__ float g_sp[CC];
__device__ float g_sn[CC];
__device__ float g_bf[CC];

// ---- L2 evict_last cache-policy ops (params + out; x goes via cp.async) ----
__device__ __forceinline__ unsigned long long mk_policy()
{
    unsigned long long pol;
    asm volatile("createpolicy.fractional.L2::evict_last.b64 %0, 1.0;" : "=l"(pol));
    return pol;
}
__device__ __forceinline__ float4 ldg_el(const float* p, unsigned long long pol)
{
    float4 v;
    asm volatile("ld.global.nc.L2::cache_hint.v4.f32 {%0,%1,%2,%3}, [%4], %5;"
                 : "=f"(v.x), "=f"(v.y), "=f"(v.z), "=f"(v.w)
                 : "l"(p), "l"(pol));
    return v;
}
__device__ __forceinline__ float ldg_el1(const float* p, unsigned long long pol)
{
    float v;
    asm volatile("ld.global.nc.L2::cache_hint.f32 %0, [%1], %2;"
                 : "=f"(v) : "l"(p), "l"(pol));
    return v;
}
__device__ __forceinline__ void stg_el(float* p, float4 v, unsigned long long pol)
{
    asm volatile("st.global.L2::cache_hint.v4.f32 [%0], {%1,%2,%3,%4}, %5;"
                 :: "l"(p), "f"(v.x), "f"(v.y), "f"(v.z), "f"(v.w), "l"(pol)
                 : "memory");
}
// -----------------------------------------------------------------------------

// 4 threads per channel, shfl-reduced; writes SoA params.
__global__ void __launch_bounds__(256)
precompute_kernel(const float* __restrict__ w1,
                  const float* __restrict__ b1,
                  const float* __restrict__ w2,
                  const float* __restrict__ b2)
{
    int t = blockIdx.x * 256 + threadIdx.x;
    int c = t >> 2;
    int part = t & 3;
    if (c >= CC) return;

    unsigned long long pol = mk_policy();
    size_t off = ((size_t)c * 4 + part) * 4;
    float4 a = ldg_el(w1 + off, pol);
    float4 z = ldg_el(b1 + off, pol);
    float4 w = ldg_el(w2 + off, pol);

    bool ok = (z.x == 0.f) && (z.y == 0.f) && (z.z == 0.f) && (z.w == 0.f);

    float sp = 0.f, sn = 0.f, p;
    p = a.x * w.x; sp += (a.x > 0.f) ? p : 0.f; sn += (a.x < 0.f) ? p : 0.f;
    p = a.y * w.y; sp += (a.y > 0.f) ? p : 0.f; sn += (a.y < 0.f) ? p : 0.f;
    p = a.z * w.z; sp += (a.z > 0.f) ? p : 0.f; sn += (a.z < 0.f) ? p : 0.f;
    p = a.w * w.w; sp += (a.w > 0.f) ? p : 0.f; sn += (a.w < 0.f) ? p : 0.f;

    if (!ok) sp = __int_as_float(0x7fc00000);   // NaN survives the reduction

    sp += __shfl_xor_sync(0xffffffffu, sp, 1);
    sp += __shfl_xor_sync(0xffffffffu, sp, 2);
    sn += __shfl_xor_sync(0xffffffffu, sn, 1);
    sn += __shfl_xor_sync(0xffffffffu, sn, 2);

    if (part == 0) {
        if (!isfinite(sp) || !isfinite(sn)) sp = __int_as_float(0x7fc00000);
        g_sp[c] = sp;
        g_sn[c] = sn;
        g_bf[c] = ldg_el1(b2 + c, pol);
    }
}

// Exact per-element path for flagged channels (never taken on this dataset).
__device__ __noinline__ float bellows_exact(float xv, int c,
                                            const float* __restrict__ w1,
                                            const float* __restrict__ b1,
                                            const float* __restrict__ w2,
                                            float bias)
{
    float acc = 0.f;
    const float* w1r = w1 + (size_t)c * EE;
    const float* b1r = b1 + (size_t)c * EE;
    const float* w2r = w2 + (size_t)c * EE;
#pragma unroll 4
    for (int e = 0; e < EE; ++e) {
        float h = fmaxf(fmaf(xv, w1r[e], b1r[e]), 0.f);
        acc = fmaf(h, w2r[e], acc);
    }
    return fmaxf(acc + bias, 0.f);
}

__device__ __forceinline__ float bellows_fast(float xv, float sp, float sn, float bias)
{
    float s = (xv > 0.f) ? sp : sn;
    return fmaxf(fmaf(xv, s, bias), 0.f);
}

__global__ void __launch_bounds__(NTHR)
apply_kernel(const float* __restrict__ x,
             const float* __restrict__ w1,
             const float* __restrict__ b1,
             const float* __restrict__ w2,
             float* __restrict__ out)
{
    __shared__ float4 sbuf[DEPTH][NTHR];   // 16 KB staging

    const int tid   = threadIdx.x;
    const int grp   = tid & 31;            // channel-group within block
    const int slice = tid >> 5;            // row slice (warp id)
    const int g     = blockIdx.x * GRPB + grp;
    if (g >= NG) return;                   // per-thread pipeline -> safe early out
    const int c0 = g * 4;

    unsigned long long pol = mk_policy();

    // Per-channel params (L2-warm after first replay).
    float4 sp4 = ldg_el(g_sp + c0, pol);
    float4 sn4 = ldg_el(g_sn + c0, pol);
    float4 bf4 = ldg_el(g_bf + c0, pol);

    const int row0 = blockIdx.y * ROWSB + slice;     // this thread's row stride-8 walk
    const float* xp = x   + (size_t)row0 * CC + c0;
    float*       op = out + (size_t)row0 * CC + c0;
    const size_t rstride = (size_t)SLICES * CC;      // 8 rows

    // Prologue: queue DEPTH stages (one 16B cp.async each), one commit per stage.
#pragma unroll
    for (int s = 0; s < DEPTH; ++s) {
        __pipeline_memcpy_async(&sbuf[s][tid], xp + (size_t)s * rstride, 16);
        __pipeline_commit();
    }

    bool any_fb = (sp4.x != sp4.x) || (sp4.y != sp4.y) ||
                  (sp4.z != sp4.z) || (sp4.w != sp4.w);

#pragma unroll
    for (int s = 0; s < NSTAGE; ++s) {
        __pipeline_wait_prior(DEPTH - 1);            // stage s is complete
        float4 xv = sbuf[s & (DEPTH - 1)][tid];

        float4 o;
        if (!any_fb) {
            o.x = bellows_fast(xv.x, sp4.x, sn4.x, bf4.x);
            o.y = bellows_fast(xv.y, sp4.y, sn4.y, bf4.y);
            o.z = bellows_fast(xv.z, sp4.z, sn4.z, bf4.z);
            o.w = bellows_fast(xv.w, sp4.w, sn4.w, bf4.w);
        } else {
            o.x = (sp4.x != sp4.x) ? bellows_exact(xv.x, c0 + 0, w1, b1, w2, bf4.x)
                                   : bellows_fast(xv.x, sp4.x, sn4.x, bf4.x);
            o.y = (sp4.y != sp4.y) ? bellows_exact(xv.y, c0 + 1, w1, b1, w2, bf4.y)
                                   : bellows_fast(xv.y, sp4.y, sn4.y, bf4.y);
            o.z = (sp4.z != sp4.z) ? bellows_exact(xv.z, c0 + 2, w1, b1, w2, bf4.z)
                                   : bellows_fast(xv.z, sp4.z, sn4.z, bf4.z);
            o.w = (sp4.w != sp4.w) ? bellows_exact(xv.w, c0 + 3, w1, b1, w2, bf4.w)
                                   : bellows_fast(xv.w, sp4.w, sn4.w, bf4.w);
        }
        stg_el(op + (size_t)s * rstride, o, pol);

        // Refill: queue stage s+DEPTH; always commit to keep group count in sync.
        if (s + DEPTH < NSTAGE)
            __pipeline_memcpy_async(&sbuf[s & (DEPTH - 1)][tid],
                                    xp + (size_t)(s + DEPTH) * rstride, 16);
        __pipeline_commit();
    }
}

extern "C" void kernel_launch(void* const* d_in, const int* in_sizes, int n_in,
                              void* d_out, int out_size)
{
    const float* x  = (const float*)d_in[0];   // (128, 40000)
    const float* w1 = (const float*)d_in[1];   // (40000, 16)
    const float* b1 = (const float*)d_in[2];   // (40000, 16)
    const float* w2 = (const float*)d_in[3];   // (40000, 16)
    const float* b2 = (const float*)d_in[4];   // (40000,)
    float* out = (float*)d_out;                // (128, 2, 20000) == (128, 40000)

    precompute_kernel<<<(CC * 4 + 255) / 256, 256>>>(w1, b1, w2, b2);

    dim3 grid((NG + GRPB - 1) / GRPB, RSPLIT); // (313, 2) = 626 blocks
    apply_kernel<<<grid, NTHR>>>(x, w1, b1, w2, out);
}